// round 2
// baseline (speedup 1.0000x reference)
#include <cuda_runtime.h>
#include <math.h>

#define SS 2048
#define DD 512
#define NB 4

// Scratch (allocation-free: __device__ globals)
__device__ float g_W[(size_t)NB * SS * SS];   // 64 MB weight matrix
__device__ float g_l1[NB * SS];               // L1 row sums
__device__ float g_m2[NB * SS];               // |M_i|^2
__device__ float g_v2[NB * SS];               // |V_j|^2

// ---------------------------------------------------------------------------
// Row squared-norms of a (NB*SS, DD) fp32 matrix. which=0 -> g_v2,
// which=1 -> g_m2 and zero g_l1 (preparing the next wdist pass).
// One block (128 threads) per row; DD=512 floats = 128 float4.
// ---------------------------------------------------------------------------
__global__ void rownorm_kernel(const float* __restrict__ X, int which) {
    int row = blockIdx.x;
    const float4* xp = reinterpret_cast<const float4*>(X + (size_t)row * DD);
    float4 v = xp[threadIdx.x];
    float s = v.x * v.x + v.y * v.y + v.z * v.z + v.w * v.w;
#pragma unroll
    for (int o = 16; o > 0; o >>= 1) s += __shfl_down_sync(0xffffffffu, s, o);
    __shared__ float ws[4];
    if ((threadIdx.x & 31) == 0) ws[threadIdx.x >> 5] = s;
    __syncthreads();
    if (threadIdx.x == 0) {
        float tot = ws[0] + ws[1] + ws[2] + ws[3];
        if (which) {
            g_m2[row] = tot;
            g_l1[row] = 0.0f;
        } else {
            g_v2[row] = tot;
        }
    }
}

// ---------------------------------------------------------------------------
// C[M,N] = Amat[M,K] @ B[K,N], row-major, batched over blockIdx.z.
// use_w  : source A operand from g_W instead of the external pointer.
// use_l1 : scale row i of output by 1/max(g_l1[row], 1e-12).
// Tile 128x128, K-chunk 16, 256 threads, 8x8 accum per thread.
// ---------------------------------------------------------------------------
__global__ void __launch_bounds__(256, 2)
gemm_rn_kernel(const float* __restrict__ Aext, const float* __restrict__ B,
               float* __restrict__ C, int K, int N,
               size_t sA, size_t sB, size_t sC, int use_w, int use_l1) {
    __shared__ float As[16][132];   // transposed A tile, padded (conflict-free stores)
    __shared__ float Bs[16][128];

    int b = blockIdx.z;
    const float* A = (use_w ? g_W : Aext) + (size_t)b * sA;
    B += (size_t)b * sB;
    C += (size_t)b * sC;

    int m0 = blockIdx.y * 128, n0 = blockIdx.x * 128;
    int tid = threadIdx.x;
    int rg = tid >> 4, cg = tid & 15;

    float acc[8][8];
#pragma unroll
    for (int i = 0; i < 8; i++)
#pragma unroll
        for (int j = 0; j < 8; j++) acc[i][j] = 0.0f;

    for (int k0 = 0; k0 < K; k0 += 16) {
#pragma unroll
        for (int q = 0; q < 2; q++) {
            int idx = tid + q * 256;
            // A tile: 128 rows x 16 k, stored transposed As[k][m]
            int row = idx >> 2, kq = (idx & 3) << 2;
            float4 va = *reinterpret_cast<const float4*>(
                A + (size_t)(m0 + row) * K + k0 + kq);
            As[kq + 0][row] = va.x;
            As[kq + 1][row] = va.y;
            As[kq + 2][row] = va.z;
            As[kq + 3][row] = va.w;
            // B tile: 16 k-rows x 128 n, direct copy
            int kr = idx >> 5, nq = (idx & 31) << 2;
            *reinterpret_cast<float4*>(&Bs[kr][nq]) =
                *reinterpret_cast<const float4*>(B + (size_t)(k0 + kr) * N + n0 + nq);
        }
        __syncthreads();
#pragma unroll
        for (int kk = 0; kk < 16; kk++) {
            float a[8], bb[8];
            *reinterpret_cast<float4*>(a)     = *reinterpret_cast<float4*>(&As[kk][rg * 8]);
            *reinterpret_cast<float4*>(a + 4) = *reinterpret_cast<float4*>(&As[kk][rg * 8 + 4]);
            *reinterpret_cast<float4*>(bb)     = *reinterpret_cast<float4*>(&Bs[kk][cg * 8]);
            *reinterpret_cast<float4*>(bb + 4) = *reinterpret_cast<float4*>(&Bs[kk][cg * 8 + 4]);
#pragma unroll
            for (int i = 0; i < 8; i++)
#pragma unroll
                for (int j = 0; j < 8; j++)
                    acc[i][j] = fmaf(a[i], bb[j], acc[i][j]);
        }
        __syncthreads();
    }

    const float* l1p = use_l1 ? (g_l1 + (size_t)b * SS) : nullptr;
#pragma unroll
    for (int i = 0; i < 8; i++) {
        int row = m0 + rg * 8 + i;
        float sc = 1.0f;
        if (l1p) sc = 1.0f / fmaxf(l1p[row], 1e-12f);
        float4 o0 = make_float4(acc[i][0] * sc, acc[i][1] * sc, acc[i][2] * sc, acc[i][3] * sc);
        float4 o1 = make_float4(acc[i][4] * sc, acc[i][5] * sc, acc[i][6] * sc, acc[i][7] * sc);
        float* cp = C + (size_t)row * N + n0 + cg * 8;
        *reinterpret_cast<float4*>(cp)     = o0;
        *reinterpret_cast<float4*>(cp + 4) = o1;
    }
}

// ---------------------------------------------------------------------------
// W[b,i,j] = A[b,i,j] / (sqrt(max(|M_i|^2 + |V_j|^2 - 2 M_i.V_j, 0)) + 0.01)
// plus partial L1 row sums (atomicAdd into g_l1).
// GEMM M @ V^T over K=DD with elementwise epilogue.
// ---------------------------------------------------------------------------
__global__ void __launch_bounds__(256, 2)
wdist_kernel(const float* __restrict__ M, const float* __restrict__ V,
             const float* __restrict__ A) {
    __shared__ float Ms[16][132];
    __shared__ float Vs[16][132];

    int b = blockIdx.z;
    const float* Mp = M + (size_t)b * SS * DD;
    const float* Vp = V + (size_t)b * SS * DD;
    const float* Ap = A + (size_t)b * SS * SS;
    float* Wp = g_W + (size_t)b * SS * SS;

    int i0 = blockIdx.y * 128, j0 = blockIdx.x * 128;
    int tid = threadIdx.x;
    int rg = tid >> 4, cg = tid & 15;

    float acc[8][8];
#pragma unroll
    for (int i = 0; i < 8; i++)
#pragma unroll
        for (int j = 0; j < 8; j++) acc[i][j] = 0.0f;

    for (int k0 = 0; k0 < DD; k0 += 16) {
#pragma unroll
        for (int q = 0; q < 2; q++) {
            int idx = tid + q * 256;
            int row = idx >> 2, kq = (idx & 3) << 2;
            float4 vm = *reinterpret_cast<const float4*>(
                Mp + (size_t)(i0 + row) * DD + k0 + kq);
            Ms[kq + 0][row] = vm.x;
            Ms[kq + 1][row] = vm.y;
            Ms[kq + 2][row] = vm.z;
            Ms[kq + 3][row] = vm.w;
            float4 vv = *reinterpret_cast<const float4*>(
                Vp + (size_t)(j0 + row) * DD + k0 + kq);
            Vs[kq + 0][row] = vv.x;
            Vs[kq + 1][row] = vv.y;
            Vs[kq + 2][row] = vv.z;
            Vs[kq + 3][row] = vv.w;
        }
        __syncthreads();
#pragma unroll
        for (int kk = 0; kk < 16; kk++) {
            float a[8], bb[8];
            *reinterpret_cast<float4*>(a)     = *reinterpret_cast<float4*>(&Ms[kk][rg * 8]);
            *reinterpret_cast<float4*>(a + 4) = *reinterpret_cast<float4*>(&Ms[kk][rg * 8 + 4]);
            *reinterpret_cast<float4*>(bb)     = *reinterpret_cast<float4*>(&Vs[kk][cg * 8]);
            *reinterpret_cast<float4*>(bb + 4) = *reinterpret_cast<float4*>(&Vs[kk][cg * 8 + 4]);
#pragma unroll
            for (int i = 0; i < 8; i++)
#pragma unroll
                for (int j = 0; j < 8; j++)
                    acc[i][j] = fmaf(a[i], bb[j], acc[i][j]);
        }
        __syncthreads();
    }

    float m2r[8], v2c[8];
#pragma unroll
    for (int i = 0; i < 8; i++) m2r[i] = g_m2[b * SS + i0 + rg * 8 + i];
#pragma unroll
    for (int j = 0; j < 8; j++) v2c[j] = g_v2[b * SS + j0 + cg * 8 + j];

#pragma unroll
    for (int i = 0; i < 8; i++) {
        size_t base = (size_t)(i0 + rg * 8 + i) * SS + j0 + cg * 8;
        float4 a0 = *reinterpret_cast<const float4*>(Ap + base);
        float4 a1 = *reinterpret_cast<const float4*>(Ap + base + 4);
        float av[8] = {a0.x, a0.y, a0.z, a0.w, a1.x, a1.y, a1.z, a1.w};
        float w[8];
        float rs = 0.0f;
#pragma unroll
        for (int j = 0; j < 8; j++) {
            float d2 = m2r[i] + v2c[j] - 2.0f * acc[i][j];
            float dist = sqrtf(fmaxf(d2, 0.0f));
            w[j] = av[j] * __frcp_rn(dist + 0.01f);
            rs += fabsf(w[j]);
        }
        *reinterpret_cast<float4*>(Wp + base)     = make_float4(w[0], w[1], w[2], w[3]);
        *reinterpret_cast<float4*>(Wp + base + 4) = make_float4(w[4], w[5], w[6], w[7]);
        // reduce row-sum across the 16 column-group lanes (width-16 shfl)
#pragma unroll
        for (int o = 8; o > 0; o >>= 1) rs += __shfl_down_sync(0xffffffffu, rs, o, 16);
        if (cg == 0) atomicAdd(&g_l1[b * SS + i0 + rg * 8 + i], rs);
    }
}

// ---------------------------------------------------------------------------
extern "C" void kernel_launch(void* const* d_in, const int* in_sizes, int n_in,
                              void* d_out, int out_size) {
    const float* A = (const float*)d_in[0];  // (4, 2048, 2048)
    const float* V = (const float*)d_in[1];  // (4, 2048, 512)
    float* M = (float*)d_out;                // (4, 2048, 512)

    dim3 gemm_grid(DD / 128, SS / 128, NB);  // (4, 16, 4)
    dim3 wgrid(SS / 128, SS / 128, NB);      // (16, 16, 4)

    // |V_j|^2 once
    rownorm_kernel<<<NB * SS, 128>>>(V, 0);
    // M0 = A @ V
    gemm_rn_kernel<<<gemm_grid, 256>>>(A, V, M, SS, DD,
                                       (size_t)SS * SS, (size_t)SS * DD,
                                       (size_t)SS * DD, 0, 0);
    for (int it = 0; it < 3; ++it) {
        // |M_i|^2 and zero l1
        rownorm_kernel<<<NB * SS, 128>>>(M, 1);
        // W = A / (dist + eps), l1 = sum_j |W|
        wdist_kernel<<<wgrid, 256>>>(M, V, A);
        // M = diag(1/max(l1,1e-12)) * (W @ V)
        gemm_rn_kernel<<<gemm_grid, 256>>>(nullptr, V, M, SS, DD,
                                           (size_t)SS * SS, (size_t)SS * DD,
                                           (size_t)SS * DD, 1, 1);
    }
}

// round 5
// speedup vs baseline: 1.9136x; 1.9136x over previous
#include <cuda_runtime.h>
#include <math.h>
#include <stdint.h>

#define SS 2048
#define DD 512
#define NB 4
#define KC 32
#define NTHREADS 256
#define LDSW 36                         // smem row stride in floats (bank-conflict-free)
#define STAGE_U32 (2 * 128 * LDSW)      // X tile + Y tile, uint32 each
#define SMEM_DYN  (2 * STAGE_U32 * 4)   // 2 stages, bytes (73728)

// ---------------- scratch (allocation-free device globals) ----------------
__device__ float g_W[(size_t)NB * SS * SS];    // 64 MB weight matrix
__device__ float g_VT[(size_t)NB * DD * SS];   // 16 MB V transposed [n][k]
__device__ float g_l1[NB * SS];
__device__ float g_m2[NB * SS];
__device__ float g_v2[NB * SS];

// ---------------- helpers ----------------
__device__ __forceinline__ uint32_t f2tf32(float x) {
    uint32_t r;
    asm("cvt.rna.tf32.f32 %0, %1;" : "=r"(r) : "f"(x));
    return r;
}
__device__ __forceinline__ void mma_tf32(float* c, const uint32_t* a, const uint32_t* b) {
    asm volatile(
        "mma.sync.aligned.m16n8k8.row.col.f32.tf32.tf32.f32 "
        "{%0,%1,%2,%3}, {%4,%5,%6,%7}, {%8,%9}, {%0,%1,%2,%3};"
        : "+f"(c[0]), "+f"(c[1]), "+f"(c[2]), "+f"(c[3])
        : "r"(a[0]), "r"(a[1]), "r"(a[2]), "r"(a[3]), "r"(b[0]), "r"(b[1]));
}

// ---------------------------------------------------------------------------
// Stage a 128x32 K-major tile of X and of Y into smem as rna-rounded tf32.
// ---------------------------------------------------------------------------
__device__ __forceinline__ void stage_load(const float* __restrict__ X,
                                           const float* __restrict__ Y,
                                           int ldx, int ldy, int m0, int n0, int k0,
                                           uint32_t* __restrict__ st, int tid) {
    uint32_t* xs = st;
    uint32_t* ys = st + 128 * LDSW;
#pragma unroll
    for (int p = 0; p < 4; ++p) {
        int idx = tid + p * NTHREADS;
        int row = idx >> 3, kq = (idx & 7) << 2;
        float4 v = *reinterpret_cast<const float4*>(
            X + (size_t)(m0 + row) * ldx + k0 + kq);
        uint4 t = make_uint4(f2tf32(v.x), f2tf32(v.y), f2tf32(v.z), f2tf32(v.w));
        *reinterpret_cast<uint4*>(xs + row * LDSW + kq) = t;
    }
#pragma unroll
    for (int p = 0; p < 4; ++p) {
        int idx = tid + p * NTHREADS;
        int row = idx >> 3, kq = (idx & 7) << 2;
        float4 v = *reinterpret_cast<const float4*>(
            Y + (size_t)(n0 + row) * ldy + k0 + kq);
        uint4 t = make_uint4(f2tf32(v.x), f2tf32(v.y), f2tf32(v.z), f2tf32(v.w));
        *reinterpret_cast<uint4*>(ys + row * LDSW + kq) = t;
    }
}

// ---------------------------------------------------------------------------
// One KC=32 chunk of MMAs. Warp tile 64(m) x 32(n): 4 m-frags x 4 n-frags.
// Fragment layout (m16n8k8 tf32): g = lane>>2, tg = lane&3.
// ---------------------------------------------------------------------------
__device__ __forceinline__ void compute_chunk(const uint32_t* __restrict__ st,
                                              float acc[4][4][4],
                                              int wm, int wn, int g, int tg) {
    const uint32_t* xs = st;
    const uint32_t* ys = st + 128 * LDSW;
#pragma unroll
    for (int ks = 0; ks < 4; ++ks) {
        int kk = ks * 8;
        uint32_t af[4][4], bf[4][2];
#pragma unroll
        for (int mf = 0; mf < 4; ++mf) {
            int rb = wm * 64 + mf * 16;
            af[mf][0] = xs[(rb + g) * LDSW + kk + tg];
            af[mf][1] = xs[(rb + 8 + g) * LDSW + kk + tg];
            af[mf][2] = xs[(rb + g) * LDSW + kk + tg + 4];
            af[mf][3] = xs[(rb + 8 + g) * LDSW + kk + tg + 4];
        }
#pragma unroll
        for (int nf = 0; nf < 4; ++nf) {
            int nb = wn * 32 + nf * 8;
            bf[nf][0] = ys[(nb + g) * LDSW + kk + tg];
            bf[nf][1] = ys[(nb + g) * LDSW + kk + tg + 4];
        }
#pragma unroll
        for (int mf = 0; mf < 4; ++mf)
#pragma unroll
            for (int nf = 0; nf < 4; ++nf)
                mma_tf32(acc[mf][nf], af[mf], bf[nf]);
    }
}

// ---------------------------------------------------------------------------
// Double-buffered mainloop: acc += X[m0:m0+128,:] @ Y[n0:n0+128,:]^T, K=nch*KC.
// ---------------------------------------------------------------------------
__device__ __forceinline__ void mainloop(const float* X, const float* Y,
                                         int ldx, int ldy, int nch,
                                         int m0, int n0, uint32_t* dyn,
                                         float acc[4][4][4],
                                         int tid, int wm, int wn, int g, int tg) {
    stage_load(X, Y, ldx, ldy, m0, n0, 0, dyn, tid);
    __syncthreads();
    for (int ch = 0; ch < nch; ++ch) {
        if (ch + 1 < nch)
            stage_load(X, Y, ldx, ldy, m0, n0, (ch + 1) * KC,
                       dyn + ((ch + 1) & 1) * STAGE_U32, tid);
        compute_chunk(dyn + (ch & 1) * STAGE_U32, acc, wm, wn, g, tg);
        __syncthreads();
    }
}

// ---------------------------------------------------------------------------
// Row squared-norms; which=0 -> g_v2, which=1 -> g_m2 + zero g_l1.
// ---------------------------------------------------------------------------
__global__ void rownorm_kernel(const float* __restrict__ X, int which) {
    int row = blockIdx.x;
    const float4* xp = reinterpret_cast<const float4*>(X + (size_t)row * DD);
    float4 v = xp[threadIdx.x];
    float s = v.x * v.x + v.y * v.y + v.z * v.z + v.w * v.w;
#pragma unroll
    for (int o = 16; o > 0; o >>= 1) s += __shfl_down_sync(0xffffffffu, s, o);
    __shared__ float ws[4];
    if ((threadIdx.x & 31) == 0) ws[threadIdx.x >> 5] = s;
    __syncthreads();
    if (threadIdx.x == 0) {
        float tot = ws[0] + ws[1] + ws[2] + ws[3];
        if (which) { g_m2[row] = tot; g_l1[row] = 0.0f; }
        else       { g_v2[row] = tot; }
    }
}

// ---------------------------------------------------------------------------
// VT[b][n][k] = V[b][k][n]   (32x32 smem transpose tiles)
// ---------------------------------------------------------------------------
__global__ void transpose_kernel(const float* __restrict__ V) {
    __shared__ float t[32][33];
    int b = blockIdx.z;
    const float* Vp = V + (size_t)b * SS * DD;
    float* Tp = g_VT + (size_t)b * DD * SS;
    int x0 = blockIdx.x * 32;  // n (0..511)
    int y0 = blockIdx.y * 32;  // k (0..2047)
    int tx = threadIdx.x & 31, ty = threadIdx.x >> 5;
#pragma unroll
    for (int i = ty; i < 32; i += 8)
        t[i][tx] = Vp[(size_t)(y0 + i) * DD + x0 + tx];
    __syncthreads();
#pragma unroll
    for (int i = ty; i < 32; i += 8)
        Tp[(size_t)(x0 + i) * SS + y0 + tx] = t[tx][i];
}

// ---------------------------------------------------------------------------
// GEMM: C[m, n] = scale(m) * sum_k Xop[m,k] * VT[n,k]   (N = DD = 512)
// use_w: Xop = g_W.  use_l1: scale = 1/max(l1[m], 1e-12).
// ---------------------------------------------------------------------------
__global__ void __launch_bounds__(NTHREADS, 2)
gemm_tc(const float* __restrict__ Aext, float* __restrict__ C,
        int use_w, int use_l1) {
    extern __shared__ uint32_t dyn[];
    int tid = threadIdx.x;
    int wid = tid >> 5, lane = tid & 31;
    int wm = wid >> 2, wn = wid & 3;
    int g = lane >> 2, tg = lane & 3;
    int b = blockIdx.z;
    int n0 = blockIdx.x * 128, m0 = blockIdx.y * 128;
    const float* X = (use_w ? g_W : Aext) + (size_t)b * SS * SS;
    const float* Y = g_VT + (size_t)b * DD * SS;
    C += (size_t)b * SS * DD;

    float acc[4][4][4];
#pragma unroll
    for (int i = 0; i < 4; ++i)
#pragma unroll
        for (int j = 0; j < 4; ++j)
#pragma unroll
            for (int e = 0; e < 4; ++e) acc[i][j][e] = 0.0f;

    mainloop(X, Y, SS, SS, SS / KC, m0, n0, dyn, acc, tid, wm, wn, g, tg);

#pragma unroll
    for (int mf = 0; mf < 4; ++mf) {
        int r1 = m0 + wm * 64 + mf * 16 + g;
        int r2 = r1 + 8;
        float s1 = 1.0f, s2 = 1.0f;
        if (use_l1) {
            s1 = 1.0f / fmaxf(g_l1[b * SS + r1], 1e-12f);
            s2 = 1.0f / fmaxf(g_l1[b * SS + r2], 1e-12f);
        }
#pragma unroll
        for (int nf = 0; nf < 4; ++nf) {
            int col = n0 + wn * 32 + nf * 8 + 2 * tg;
            float2 o1 = make_float2(acc[mf][nf][0] * s1, acc[mf][nf][1] * s1);
            float2 o2 = make_float2(acc[mf][nf][2] * s2, acc[mf][nf][3] * s2);
            *reinterpret_cast<float2*>(C + (size_t)r1 * DD + col) = o1;
            *reinterpret_cast<float2*>(C + (size_t)r2 * DD + col) = o2;
        }
    }
}

// ---------------------------------------------------------------------------
// W[i,j] = A[i,j] / (sqrt(max(m2[i]+v2[j]-2*M_i.V_j, 0)) + 0.01) + l1 row sums.
// ---------------------------------------------------------------------------
__global__ void __launch_bounds__(NTHREADS, 2)
wdist_tc(const float* __restrict__ M, const float* __restrict__ V,
         const float* __restrict__ A) {
    extern __shared__ uint32_t dyn[];
    int tid = threadIdx.x;
    int wid = tid >> 5, lane = tid & 31;
    int wm = wid >> 2, wn = wid & 3;
    int g = lane >> 2, tg = lane & 3;
    int b = blockIdx.z;
    int j0 = blockIdx.x * 128, i0 = blockIdx.y * 128;
    const float* Mp = M + (size_t)b * SS * DD;
    const float* Vp = V + (size_t)b * SS * DD;
    const float* Ap = A + (size_t)b * SS * SS;
    float* Wp = g_W + (size_t)b * SS * SS;
    const float* v2p = g_v2 + b * SS;

    float acc[4][4][4];
#pragma unroll
    for (int i = 0; i < 4; ++i)
#pragma unroll
        for (int j = 0; j < 4; ++j)
#pragma unroll
            for (int e = 0; e < 4; ++e) acc[i][j][e] = 0.0f;

    mainloop(Mp, Vp, DD, DD, DD / KC, i0, j0, dyn, acc, tid, wm, wn, g, tg);

#pragma unroll
    for (int mf = 0; mf < 4; ++mf) {
        int r1 = i0 + wm * 64 + mf * 16 + g;
        int r2 = r1 + 8;
        float m21 = g_m2[b * SS + r1];
        float m22 = g_m2[b * SS + r2];
        float rs1 = 0.0f, rs2 = 0.0f;
#pragma unroll
        for (int nf = 0; nf < 4; ++nf) {
            int jj = j0 + wn * 32 + nf * 8 + 2 * tg;
            float v2a = v2p[jj], v2b = v2p[jj + 1];
            float2 a1 = *reinterpret_cast<const float2*>(Ap + (size_t)r1 * SS + jj);
            float2 a2 = *reinterpret_cast<const float2*>(Ap + (size_t)r2 * SS + jj);
            float d;
            d = sqrtf(fmaxf(m21 + v2a - 2.0f * acc[mf][nf][0], 0.0f));
            float w0 = a1.x * __frcp_rn(d + 0.01f);
            d = sqrtf(fmaxf(m21 + v2b - 2.0f * acc[mf][nf][1], 0.0f));
            float w1 = a1.y * __frcp_rn(d + 0.01f);
            d = sqrtf(fmaxf(m22 + v2a - 2.0f * acc[mf][nf][2], 0.0f));
            float w2 = a2.x * __frcp_rn(d + 0.01f);
            d = sqrtf(fmaxf(m22 + v2b - 2.0f * acc[mf][nf][3], 0.0f));
            float w3 = a2.y * __frcp_rn(d + 0.01f);
            rs1 += fabsf(w0) + fabsf(w1);
            rs2 += fabsf(w2) + fabsf(w3);
            *reinterpret_cast<float2*>(Wp + (size_t)r1 * SS + jj) = make_float2(w0, w1);
            *reinterpret_cast<float2*>(Wp + (size_t)r2 * SS + jj) = make_float2(w2, w3);
        }
        // reduce across the quad (lanes differing in tg only)
        rs1 += __shfl_xor_sync(0xffffffffu, rs1, 1);
        rs1 += __shfl_xor_sync(0xffffffffu, rs1, 2);
        rs2 += __shfl_xor_sync(0xffffffffu, rs2, 1);
        rs2 += __shfl_xor_sync(0xffffffffu, rs2, 2);
        if (tg == 0) {
            atomicAdd(&g_l1[b * SS + r1], rs1);
            atomicAdd(&g_l1[b * SS + r2], rs2);
        }
    }
}

// ---------------------------------------------------------------------------
extern "C" void kernel_launch(void* const* d_in, const int* in_sizes, int n_in,
                              void* d_out, int out_size) {
    const float* A = (const float*)d_in[0];  // (4, 2048, 2048)
    const float* V = (const float*)d_in[1];  // (4, 2048, 512)
    float* M = (float*)d_out;                // (4, 2048, 512)

    cudaFuncSetAttribute(gemm_tc, cudaFuncAttributeMaxDynamicSharedMemorySize, SMEM_DYN);
    cudaFuncSetAttribute(wdist_tc, cudaFuncAttributeMaxDynamicSharedMemorySize, SMEM_DYN);

    dim3 ggrid(DD / 128, SS / 128, NB);  // (4, 16, 4)
    dim3 wgrid(SS / 128, SS / 128, NB);  // (16, 16, 4)

    transpose_kernel<<<dim3(DD / 32, SS / 32, NB), 256>>>(V);
    rownorm_kernel<<<NB * SS, 128>>>(V, 0);
    gemm_tc<<<ggrid, NTHREADS, SMEM_DYN>>>(A, M, 0, 0);
    for (int it = 0; it < 3; ++it) {
        rownorm_kernel<<<NB * SS, 128>>>(M, 1);
        wdist_tc<<<wgrid, NTHREADS, SMEM_DYN>>>(M, V, A);
        gemm_tc<<<ggrid, NTHREADS, SMEM_DYN>>>(nullptr, M, 1, 1);
    }
}